// round 14
// baseline (speedup 1.0000x reference)
#include <cuda_runtime.h>
#include <cuda_bf16.h>
#include <math.h>
#include <stdint.h>

#define N_ROWS 4096
#define D      256
#define TWO_N  8192
#define BM 128
#define BN 128
#define BK 128                     // int8 elements per k-chunk
#define NKT (D / BK)               // 2 k-chunks
#define NCOLTILES 64
#define NTILES 1552
#define GRID_GEMM 296              // 2 CTAs/SM: all co-resident -> spin barriers safe
#define NWARPS_G (GRID_GEMM * 8)   // 2368 grid warps

// exp(x/T) = 2^(x * invT * log2(e))
__device__ __constant__ float c_l2T  = 20.609929f;
__device__ __constant__ float c_invT = 14.285714285714286f;

// Scratch (device globals; no allocation anywhere)
__device__ int8_t  g_q[TWO_N * D];       // int8 quantized normalized rows
__device__ float   g_rs[TWO_N];          // per-row dequant scale (absmax/127)
__device__ float   g_partial[N_ROWS * NCOLTILES];
__device__ float   g_blocksum[GRID_GEMM];
__device__ int     g_bar = 0;            // monotone grid barrier counter
__device__ int     g_counter = 0;        // loss last-block counter

// ---------------------------------------------------------------------------
// PTX helpers (sm_80+ baseline only)
// ---------------------------------------------------------------------------
__device__ __forceinline__ uint32_t smem_to_u32(const void* p) {
    uint32_t a;
    asm("{ .reg .u64 t; cvta.to.shared.u64 t, %1; cvt.u32.u64 %0, t; }" : "=r"(a) : "l"(p));
    return a;
}
__device__ __forceinline__ float ex2(float x) {
    float r;
    asm("ex2.approx.ftz.f32 %0, %1;" : "=f"(r) : "f"(x));
    return r;
}
#define CP_ASYNC16(dst, src) \
    asm volatile("cp.async.cg.shared.global [%0], [%1], 16;" :: "r"(dst), "l"(src))
#define CP_COMMIT() asm volatile("cp.async.commit_group;" ::: "memory")
#define CP_WAIT(n)  asm volatile("cp.async.wait_group %0;" :: "n"(n) : "memory")

__device__ __forceinline__ void ldsm4(uint32_t* r, uint32_t addr) {
    asm volatile("ldmatrix.sync.aligned.m8n8.x4.shared.b16 {%0,%1,%2,%3}, [%4];"
        : "=r"(r[0]), "=r"(r[1]), "=r"(r[2]), "=r"(r[3]) : "r"(addr));
}
__device__ __forceinline__ void imma16832(int* c, const uint32_t* a,
                                          uint32_t b0, uint32_t b1) {
    asm volatile("mma.sync.aligned.m16n8k32.row.col.s32.s8.s8.s32 "
        "{%0,%1,%2,%3}, {%4,%5,%6,%7}, {%8,%9}, {%0,%1,%2,%3};"
        : "+r"(c[0]), "+r"(c[1]), "+r"(c[2]), "+r"(c[3])
        : "r"(a[0]), "r"(a[1]), "r"(a[2]), "r"(a[3]), "r"(b0), "r"(b1));
}

__device__ __forceinline__ uint32_t swadr(uint32_t base, int rowByte, int rm, int ch) {
    return base + rowByte + ((ch ^ rm) << 4);
}

// Monotone device-wide barrier: each CTA adds 1; spin until counter >= target.
// Counter never resets mid-kernel (reset only at the very end, after all CTAs
// provably observed the final target). Safe: grid=296 is fully co-resident
// (2 CTAs/SM x 148 SMs via launch_bounds + smem budget).
__device__ __forceinline__ void grid_barrier(int target) {
    __syncthreads();
    if (threadIdx.x == 0) {
        __threadfence();
        atomicAdd(&g_bar, 1);
        int v;
        do {
            asm volatile("ld.acquire.gpu.global.b32 %0, [%1];"
                         : "=r"(v) : "l"(&g_bar));
        } while (v < target);
    }
    __syncthreads();
}

#define STAGE_BYTES 32768
#define SCRATCH_OFF (2 * STAGE_BYTES)            // 65536: epilogue scratch
#define SMEM_TOTAL  (SCRATCH_OFF + 3072)         // 68608 B (2 CTAs/SM fits)

// ---------------------------------------------------------------------------
// Stage loader: A 128x128B (region 0) + B 128x128B (region +16384).
// ---------------------------------------------------------------------------
__device__ __forceinline__ void load_stage(uint32_t stageAddr, int kt,
                                           int rowBase, int colBase, int tid) {
    const int kOff = kt * BK;
    #pragma unroll
    for (int i = 0; i < 8; i++) {
        const int v = i * 256 + tid;              // 0..2047
        const int half = v >> 10;                 // 0 = A, 1 = B
        const int r = (v >> 3) & 127, c = v & 7;
        const int gRow = half ? (colBase + r) : (rowBase + r);
        const void* src = g_q + (size_t)gRow * D + kOff + c * 16;
        const uint32_t dst = stageAddr + half * 16384 + r * 128 + ((c ^ (r & 7)) << 4);
        CP_ASYNC16(dst, src);
    }
}

// Tile decode: b<1024 -> right half; else triangular (symmetric Z1Z1^T part).
__device__ __forceinline__ void decode_tile(int b, int& bx, int& ct, bool& sym) {
    if (b < 1024) {
        bx = b >> 5; ct = 32 + (b & 31); sym = false;
    } else {
        const int t = b - 1024;
        int e = (int)((sqrtf(8.0f * t + 1.0f) - 1.0f) * 0.5f);
        while ((e + 1) * (e + 2) / 2 <= t) e++;
        while (e * (e + 1) / 2 > t) e--;
        bx = e; ct = t - e * (e + 1) / 2; sym = (ct != bx);
    }
}

// ---------------------------------------------------------------------------
// Per-warp loss for one row (dp4a, self-consistent with the int8 GEMM).
// Returns loss on lane 0 (garbage elsewhere).
// ---------------------------------------------------------------------------
__device__ __forceinline__ float row_loss(int row, int lane) {
    float total = g_partial[(size_t)row * NCOLTILES + lane]
                + g_partial[(size_t)row * NCOLTILES + lane + 32];

    const uint2 qa = reinterpret_cast<const uint2*>(g_q + (size_t)row * D)[lane];
    const uint2 qb = reinterpret_cast<const uint2*>(g_q + (size_t)(N_ROWS + row) * D)[lane];
    const uint2 qc = reinterpret_cast<const uint2*>(g_q + (size_t)N_ROWS * D)[lane];

    int dpi = __dp4a((int)qa.x, (int)qb.x, 0); dpi = __dp4a((int)qa.y, (int)qb.y, dpi);
    int d0i = __dp4a((int)qa.x, (int)qc.x, 0); d0i = __dp4a((int)qa.y, (int)qc.y, d0i);
    int dii = __dp4a((int)qa.x, (int)qa.x, 0); dii = __dp4a((int)qa.y, (int)qa.y, dii);

    #pragma unroll
    for (int off = 16; off > 0; off >>= 1) {
        total += __shfl_xor_sync(0xffffffffu, total, off);
        dpi   += __shfl_xor_sync(0xffffffffu, dpi, off);
        d0i   += __shfl_xor_sync(0xffffffffu, d0i, off);
        dii   += __shfl_xor_sync(0xffffffffu, dii, off);
    }
    const float ra = g_rs[row];
    const float rb = g_rs[N_ROWS + row];
    const float rc = g_rs[N_ROWS];
    const float dp    = __int2float_rn(dpi) * ra * rb;
    const float d0    = __int2float_rn(d0i) * ra * rc;
    const float dii_f = __int2float_rn(dii) * ra * ra;
    // exclude col n (d0) and replace quantized diagonal by exact exp(1/T)
    float sum_negs = total - ex2(d0 * c_l2T) - ex2(dii_f * c_l2T) + ex2(c_l2T);
    return logf(sum_negs) - dp * c_invT;
}

// ---------------------------------------------------------------------------
// THE fused kernel: normalize+quant -> barrier -> IMMA sim-GEMM -> barrier ->
// loss + mean. Grid 296 (all co-resident).
// ---------------------------------------------------------------------------
__global__ void __launch_bounds__(256, 2) fused_kernel(const float* __restrict__ z1,
                                                       const float* __restrict__ z2,
                                                       float* __restrict__ out) {
    extern __shared__ char smem[];
    const uint32_t smem_u32 = smem_to_u32(smem);
    const int tid  = threadIdx.x;
    const int lane = tid & 31;
    const int w    = tid >> 5;

    // ================= Phase 0: normalize + int8 quant =================
    #pragma unroll 1
    for (int row = blockIdx.x * 8 + w; row < TWO_N; row += NWARPS_G) {
        const float* src = (row < N_ROWS) ? (z1 + (size_t)row * D)
                                          : (z2 + (size_t)(row - N_ROWS) * D);
        float4 a = reinterpret_cast<const float4*>(src)[lane];
        float4 b = reinterpret_cast<const float4*>(src)[lane + 32];
        float ss = a.x*a.x + a.y*a.y + a.z*a.z + a.w*a.w
                 + b.x*b.x + b.y*b.y + b.z*b.z + b.w*b.w;
        #pragma unroll
        for (int off = 16; off > 0; off >>= 1)
            ss += __shfl_xor_sync(0xffffffffu, ss, off);
        const float scale = 1.0f / fmaxf(sqrtf(ss), 1e-12f);

        float v[8] = {a.x*scale, a.y*scale, a.z*scale, a.w*scale,
                      b.x*scale, b.y*scale, b.z*scale, b.w*scale};
        float m = 0.0f;
        #pragma unroll
        for (int i = 0; i < 8; i++) m = fmaxf(m, fabsf(v[i]));
        #pragma unroll
        for (int off = 16; off > 0; off >>= 1)
            m = fmaxf(m, __shfl_xor_sync(0xffffffffu, m, off));

        const float qs = 127.0f / m;
        int q[8];
        #pragma unroll
        for (int i = 0; i < 8; i++) q[i] = __float2int_rn(v[i] * qs);
        uint32_t w0 = (q[0] & 255) | ((q[1] & 255) << 8) | ((q[2] & 255) << 16) | (q[3] << 24);
        uint32_t w1 = (q[4] & 255) | ((q[5] & 255) << 8) | ((q[6] & 255) << 16) | (q[7] << 24);
        uint32_t* dst = reinterpret_cast<uint32_t*>(g_q + (size_t)row * D);
        dst[lane]      = w0;
        dst[lane + 32] = w1;
        if (lane == 0) g_rs[row] = m * (1.0f / 127.0f);
    }

    grid_barrier(GRID_GEMM);          // all quantized rows visible

    // ================= Phase 1: IMMA GEMM (R12 static loop) =================
    {
        const int warpM = w >> 1;
        const int warpN = w & 1;
        const int aRow  = warpM * 32 + (lane & 7) + ((lane >> 3) & 1) * 8;
        const int aCh   = (lane >> 4) & 1;
        const int aRm   = aRow & 7;
        const int bRow  = warpN * 64 + (lane & 7) + ((lane >> 4) & 1) * 8;
        const int bCh   = (lane >> 3) & 1;
        const int bRm   = bRow & 7;
        const int aRowByte[2] = {aRow * 128, (aRow + 16) * 128};
        const int bRowByte[4] = {bRow * 128, (bRow + 16) * 128,
                                 (bRow + 32) * 128, (bRow + 48) * 128};

        float* rowScratch = reinterpret_cast<float*>(smem + SCRATCH_OFF);
        float* colScratch = reinterpret_cast<float*>(smem + SCRATCH_OFF) + 256;

        int tile = blockIdx.x;
        int bx, colTile; bool sym;
        decode_tile(tile, bx, colTile, sym);
        int rowBase = bx * BM, colBase = colTile * BN;

        int chunk = 0;
        load_stage(smem_u32, 0, rowBase, colBase, tid);
        CP_COMMIT();

        #pragma unroll 1
        while (true) {
            const int nxtTile = tile + GRID_GEMM;
            const bool hasNext = (nxtTile < NTILES);
            int nbx = 0, nct = 0; bool nsym = false;
            if (hasNext) decode_tile(nxtTile, nbx, nct, nsym);
            const int nRowBase = nbx * BM, nColBase = nct * BN;

            int acc[2][8][4];
            #pragma unroll
            for (int mt = 0; mt < 2; mt++)
                #pragma unroll
                for (int nt = 0; nt < 8; nt++)
                    #pragma unroll
                    for (int r = 0; r < 4; r++) acc[mt][nt][r] = 0;

            #pragma unroll 1
            for (int kt = 0; kt < NKT; kt++) {
                const uint32_t stage  = smem_u32 + (uint32_t)(chunk & 1) * STAGE_BYTES;
                const uint32_t nstage = smem_u32 + (uint32_t)((chunk + 1) & 1) * STAGE_BYTES;
                if (kt + 1 < NKT) {
                    load_stage(nstage, kt + 1, rowBase, colBase, tid);
                    CP_COMMIT(); CP_WAIT(1);
                } else if (hasNext) {
                    load_stage(nstage, 0, nRowBase, nColBase, tid);
                    CP_COMMIT(); CP_WAIT(1);
                } else {
                    CP_WAIT(0);
                }
                __syncthreads();

                const uint32_t bBase = stage + 16384;
                #pragma unroll
                for (int s = 0; s < 4; s++) {
                    uint32_t ah[2][4], bh[4][4];
                    #pragma unroll
                    for (int mt = 0; mt < 2; mt++)
                        ldsm4(ah[mt], swadr(stage, aRowByte[mt], aRm, 2 * s + aCh));
                    #pragma unroll
                    for (int p = 0; p < 4; p++)
                        ldsm4(bh[p], swadr(bBase, bRowByte[p], bRm, 2 * s + bCh));
                    #pragma unroll
                    for (int mt = 0; mt < 2; mt++)
                        #pragma unroll
                        for (int nt = 0; nt < 8; nt++)
                            imma16832(acc[mt][nt], ah[mt], bh[nt >> 1][(nt & 1) * 2],
                                      bh[nt >> 1][(nt & 1) * 2 + 1]);
                }
                __syncthreads();
                chunk++;
            }

            // Epilogue: dequant + exp + row/col sums
            const float l2T = c_l2T;
            const int r8 = lane >> 2;
            float raL[4];
            #pragma unroll
            for (int mt = 0; mt < 2; mt++) {
                raL[mt * 2 + 0] = g_rs[rowBase + warpM * 32 + mt * 16 + 0 + r8] * l2T;
                raL[mt * 2 + 1] = g_rs[rowBase + warpM * 32 + mt * 16 + 8 + r8] * l2T;
            }
            float rbv[16];
            #pragma unroll
            for (int nt = 0; nt < 8; nt++) {
                const int c0 = colBase + warpN * 64 + nt * 8 + (lane & 3) * 2;
                rbv[nt * 2 + 0] = g_rs[c0];
                rbv[nt * 2 + 1] = g_rs[c0 + 1];
            }

            float rs0[2] = {0.0f, 0.0f}, rs1[2] = {0.0f, 0.0f};
            float cs[16];
            #pragma unroll
            for (int i = 0; i < 16; i++) cs[i] = 0.0f;

            #pragma unroll
            for (int mt = 0; mt < 2; mt++)
                #pragma unroll
                for (int nt = 0; nt < 8; nt++) {
                    const float f0 = __int2float_rn(acc[mt][nt][0]);
                    const float f1 = __int2float_rn(acc[mt][nt][1]);
                    const float f2 = __int2float_rn(acc[mt][nt][2]);
                    const float f3 = __int2float_rn(acc[mt][nt][3]);
                    const float e0 = ex2(f0 * raL[mt * 2 + 0] * rbv[nt * 2 + 0]);
                    const float e1 = ex2(f1 * raL[mt * 2 + 0] * rbv[nt * 2 + 1]);
                    const float e2 = ex2(f2 * raL[mt * 2 + 1] * rbv[nt * 2 + 0]);
                    const float e3 = ex2(f3 * raL[mt * 2 + 1] * rbv[nt * 2 + 1]);
                    rs0[mt] += e0 + e1;
                    rs1[mt] += e2 + e3;
                    cs[nt * 2 + 0] += e0 + e2;
                    cs[nt * 2 + 1] += e1 + e3;
                }

            #pragma unroll
            for (int off = 1; off <= 2; off <<= 1) {
                #pragma unroll
                for (int mt = 0; mt < 2; mt++) {
                    rs0[mt] += __shfl_xor_sync(0xffffffffu, rs0[mt], off);
                    rs1[mt] += __shfl_xor_sync(0xffffffffu, rs1[mt], off);
                }
            }
            if ((lane & 3) == 0) {
                #pragma unroll
                for (int mt = 0; mt < 2; mt++) {
                    rowScratch[warpN * 128 + warpM * 32 + mt * 16 + 0 + r8] = rs0[mt];
                    rowScratch[warpN * 128 + warpM * 32 + mt * 16 + 8 + r8] = rs1[mt];
                }
            }
            if (sym) {
                #pragma unroll
                for (int i = 0; i < 16; i++) {
                    #pragma unroll
                    for (int off = 4; off <= 16; off <<= 1)
                        cs[i] += __shfl_xor_sync(0xffffffffu, cs[i], off);
                }
                if (lane < 4) {
                    #pragma unroll
                    for (int nt = 0; nt < 8; nt++) {
                        colScratch[(warpN * 4 + warpM) * 64 + nt * 8 + lane * 2 + 0] = cs[nt * 2 + 0];
                        colScratch[(warpN * 4 + warpM) * 64 + nt * 8 + lane * 2 + 1] = cs[nt * 2 + 1];
                    }
                }
            }
            __syncthreads();

            if (tid < 128) {
                const float p = rowScratch[tid] + rowScratch[128 + tid];
                g_partial[(size_t)(rowBase + tid) * NCOLTILES + colTile] = p;
                if (sym) {
                    const int wn = tid >> 6, ix = tid & 63;
                    float c = colScratch[(wn * 4 + 0) * 64 + ix] + colScratch[(wn * 4 + 1) * 64 + ix]
                            + colScratch[(wn * 4 + 2) * 64 + ix] + colScratch[(wn * 4 + 3) * 64 + ix];
                    g_partial[(size_t)(colBase + tid) * NCOLTILES + bx] = c;
                }
            }
            __syncthreads();

            if (!hasNext) break;
            tile = nxtTile; bx = nbx; colTile = nct; sym = nsym;
            rowBase = nRowBase; colBase = nColBase;
        }
    }

    grid_barrier(2 * GRID_GEMM);      // all partials visible

    // ================= Phase 2: loss + mean =================
    {
        float* scratch = reinterpret_cast<float*>(smem + SCRATCH_OFF);
        __shared__ int isLast;

        const int warpGlobal = blockIdx.x * 8 + w;
        float lsum = 0.0f;
        {
            float l0 = row_loss(warpGlobal, lane);               // rows 0..2367
            if (lane == 0) lsum += l0;
            const int row2 = warpGlobal + NWARPS_G;              // rows 2368..4735
            if (row2 < N_ROWS) {
                float l1 = row_loss(row2, lane);
                if (lane == 0) lsum += l1;
            }
        }
        if (lane == 0) scratch[w] = lsum;
        __syncthreads();

        if (tid == 0) {
            float bs = 0.0f;
            #pragma unroll
            for (int i = 0; i < 8; i++) bs += scratch[i];
            g_blocksum[blockIdx.x] = bs;
            __threadfence();
            int old = atomicAdd(&g_counter, 1);
            isLast = (old == GRID_GEMM - 1);
        }
        __syncthreads();

        if (isLast) {
            float v = 0.0f;
            if (tid < GRID_GEMM) {
                asm volatile("ld.global.cg.f32 %0, [%1];" : "=f"(v)
                             : "l"(g_blocksum + tid));
            }
            if (tid + 256 < GRID_GEMM) {
                float t;
                asm volatile("ld.global.cg.f32 %0, [%1];" : "=f"(t)
                             : "l"(g_blocksum + tid + 256));
                v += t;
            }
            scratch[tid] = v;
            __syncthreads();
            #pragma unroll
            for (int stride = 128; stride > 0; stride >>= 1) {
                if (tid < stride) scratch[tid] += scratch[tid + stride];
                __syncthreads();
            }
            if (tid == 0) {
                out[0] = scratch[0] * (1.0f / N_ROWS);
                // Safe reset: every CTA observed g_bar >= 2*GRID before its
                // loss-arrive, and this block runs after ALL loss-arrives.
                g_counter = 0;
                g_bar = 0;
            }
        }
    }
}

// ---------------------------------------------------------------------------
extern "C" void kernel_launch(void* const* d_in, const int* in_sizes, int n_in,
                              void* d_out, int out_size) {
    const float* z1 = (const float*)d_in[0];
    const float* z2 = (const float*)d_in[1];
    float* out = (float*)d_out;

    cudaFuncSetAttribute(fused_kernel,
                         cudaFuncAttributeMaxDynamicSharedMemorySize, SMEM_TOTAL);

    fused_kernel<<<GRID_GEMM, 256, SMEM_TOTAL>>>(z1, z2, out);
}

// round 15
// speedup vs baseline: 1.1116x; 1.1116x over previous
#include <cuda_runtime.h>
#include <cuda_bf16.h>
#include <math.h>
#include <stdint.h>

#define N_ROWS 4096
#define D      256
#define TWO_N  8192
#define BM 128
#define BN 128
#define BK 128                     // int8 elements per k-chunk (128 bytes/row)
#define NKT (D / BK)               // 2 k-chunks
#define NCOLTILES 64
#define NLOSSBLK (N_ROWS / 8)      // 512 loss blocks
#define NTILES 1552
#define GRID_GEMM 296              // 2 CTAs per SM, persistent

// exp(x/T) = 2^(x * invT * log2(e))
__device__ __constant__ float c_l2T  = 20.609929f;
__device__ __constant__ float c_invT = 14.285714285714286f;

// Scratch (device globals; no allocation anywhere)
__device__ int8_t  g_q[TWO_N * D];       // int8 quantized normalized rows
__device__ float   g_rs[TWO_N];          // per-row dequant scale (absmax/127)
__device__ float   g_partial[N_ROWS * NCOLTILES];
__device__ float   g_blocksum[NLOSSBLK];
__device__ int     g_counter = 0;        // loss last-block counter

// ---------------------------------------------------------------------------
// PTX helpers (sm_80+ baseline only)
// ---------------------------------------------------------------------------
__device__ __forceinline__ uint32_t smem_to_u32(const void* p) {
    uint32_t a;
    asm("{ .reg .u64 t; cvta.to.shared.u64 t, %1; cvt.u32.u64 %0, t; }" : "=r"(a) : "l"(p));
    return a;
}
__device__ __forceinline__ float ex2(float x) {
    float r;
    asm("ex2.approx.ftz.f32 %0, %1;" : "=f"(r) : "f"(x));
    return r;
}
#define CP_ASYNC16(dst, src) \
    asm volatile("cp.async.cg.shared.global [%0], [%1], 16;" :: "r"(dst), "l"(src))
#define CP_COMMIT() asm volatile("cp.async.commit_group;" ::: "memory")
#define CP_WAIT(n)  asm volatile("cp.async.wait_group %0;" :: "n"(n) : "memory")

__device__ __forceinline__ void ldsm4(uint32_t* r, uint32_t addr) {
    asm volatile("ldmatrix.sync.aligned.m8n8.x4.shared.b16 {%0,%1,%2,%3}, [%4];"
        : "=r"(r[0]), "=r"(r[1]), "=r"(r[2]), "=r"(r[3]) : "r"(addr));
}
// s8 IMMA: D(s32) = A(s8 16x32) * B(s8 32x8) + D
__device__ __forceinline__ void imma16832(int* c, const uint32_t* a,
                                          uint32_t b0, uint32_t b1) {
    asm volatile("mma.sync.aligned.m16n8k32.row.col.s32.s8.s8.s32 "
        "{%0,%1,%2,%3}, {%4,%5,%6,%7}, {%8,%9}, {%0,%1,%2,%3};"
        : "+r"(c[0]), "+r"(c[1]), "+r"(c[2]), "+r"(c[3])
        : "r"(a[0]), "r"(a[1]), "r"(a[2]), "r"(a[3]), "r"(b0), "r"(b1));
}

__device__ __forceinline__ uint32_t swadr(uint32_t base, int rowByte, int rm, int ch) {
    return base + rowByte + ((ch ^ rm) << 4);
}

#define STAGE_BYTES 32768
#define SCRATCH_OFF (2 * STAGE_BYTES)            // 65536: epilogue scratch
#define SMEM_TOTAL  (SCRATCH_OFF + 3072)         // 68608 B (2 CTAs/SM fits)

// ---------------------------------------------------------------------------
// Kernel 1: L2-normalize rows -> int8 (per-row absmax quant) + scale.
// FOUR rows per warp: 8 independent float4 loads issued up front (MLP=8),
// four interleaved shuffle-reduction chains. Grid 256.
// ---------------------------------------------------------------------------
__global__ void __launch_bounds__(256) normalize_kernel(const float* __restrict__ z1,
                                                        const float* __restrict__ z2) {
    const int wid  = blockIdx.x * 8 + (threadIdx.x >> 5);
    const int lane = threadIdx.x & 31;
    const int row0 = wid * 4;

    float4 a[4], b[4];
    #pragma unroll
    for (int i = 0; i < 4; i++) {
        const int row = row0 + i;
        const float* src = (row < N_ROWS) ? (z1 + (size_t)row * D)
                                          : (z2 + (size_t)(row - N_ROWS) * D);
        a[i] = reinterpret_cast<const float4*>(src)[lane];
        b[i] = reinterpret_cast<const float4*>(src)[lane + 32];
    }

    float ss[4];
    #pragma unroll
    for (int i = 0; i < 4; i++)
        ss[i] = a[i].x*a[i].x + a[i].y*a[i].y + a[i].z*a[i].z + a[i].w*a[i].w
              + b[i].x*b[i].x + b[i].y*b[i].y + b[i].z*b[i].z + b[i].w*b[i].w;
    #pragma unroll
    for (int off = 16; off > 0; off >>= 1)
        #pragma unroll
        for (int i = 0; i < 4; i++)
            ss[i] += __shfl_xor_sync(0xffffffffu, ss[i], off);

    #pragma unroll
    for (int i = 0; i < 4; i++) {
        const int row = row0 + i;
        const float scale = 1.0f / fmaxf(sqrtf(ss[i]), 1e-12f);
        float v[8] = {a[i].x*scale, a[i].y*scale, a[i].z*scale, a[i].w*scale,
                      b[i].x*scale, b[i].y*scale, b[i].z*scale, b[i].w*scale};
        float m = 0.0f;
        #pragma unroll
        for (int j = 0; j < 8; j++) m = fmaxf(m, fabsf(v[j]));
        #pragma unroll
        for (int off = 16; off > 0; off >>= 1)
            m = fmaxf(m, __shfl_xor_sync(0xffffffffu, m, off));

        const float qs = 127.0f / m;
        int q[8];
        #pragma unroll
        for (int j = 0; j < 8; j++) q[j] = __float2int_rn(v[j] * qs);

        uint32_t w0 = (q[0] & 255) | ((q[1] & 255) << 8) | ((q[2] & 255) << 16) | (q[3] << 24);
        uint32_t w1 = (q[4] & 255) | ((q[5] & 255) << 8) | ((q[6] & 255) << 16) | (q[7] << 24);
        uint32_t* dst = reinterpret_cast<uint32_t*>(g_q + (size_t)row * D);
        dst[lane]      = w0;
        dst[lane + 32] = w1;
        if (lane == 0) g_rs[row] = m * (1.0f / 127.0f);
    }
}

// ---------------------------------------------------------------------------
// Stage loader: A 128x128B (region 0) + B 128x128B (region +16384).
// 2048 16B chunks, 8 per thread.
// ---------------------------------------------------------------------------
__device__ __forceinline__ void load_stage(uint32_t stageAddr, int kt,
                                           int rowBase, int colBase, int tid) {
    const int kOff = kt * BK;
    #pragma unroll
    for (int i = 0; i < 8; i++) {
        const int v = i * 256 + tid;              // 0..2047
        const int half = v >> 10;                 // 0 = A, 1 = B
        const int r = (v >> 3) & 127, c = v & 7;
        const int gRow = half ? (colBase + r) : (rowBase + r);
        const void* src = g_q + (size_t)gRow * D + kOff + c * 16;
        const uint32_t dst = stageAddr + half * 16384 + r * 128 + ((c ^ (r & 7)) << 4);
        CP_ASYNC16(dst, src);
    }
}

// Tile decode: b<1024 -> right half (bx=b>>5, ct=32+(b&31)); else triangular.
__device__ __forceinline__ void decode_tile(int b, int& bx, int& ct, bool& sym) {
    if (b < 1024) {
        bx = b >> 5; ct = 32 + (b & 31); sym = false;
    } else {
        const int t = b - 1024;
        int e = (int)((sqrtf(8.0f * t + 1.0f) - 1.0f) * 0.5f);
        while ((e + 1) * (e + 2) / 2 <= t) e++;
        while (e * (e + 1) / 2 > t) e--;
        bx = e; ct = t - e * (e + 1) / 2; sym = (ct != bx);
    }
}

// ---------------------------------------------------------------------------
// Kernel 2: persistent INT8-IMMA fused sim-GEMM + dequant + exp + row/col
// sums. R12 verbatim (STATIC schedule, 2-stage, 2 syncs/chunk, cross-tile
// prefetch); NKT=2 chunks of BK=128 int8; 4 k32 IMMA steps/chunk.
// ---------------------------------------------------------------------------
__global__ void __launch_bounds__(256, 2) simsum_mma_kernel() {
    extern __shared__ char smem[];
    const uint32_t smem_u32 = smem_to_u32(smem);
    const int tid = threadIdx.x;

    const int lane  = tid & 31;
    const int w     = tid >> 5;
    const int warpM = w >> 1;
    const int warpN = w & 1;

    const int aRow  = warpM * 32 + (lane & 7) + ((lane >> 3) & 1) * 8;
    const int aCh   = (lane >> 4) & 1;
    const int aRm   = aRow & 7;
    const int bRow  = warpN * 64 + (lane & 7) + ((lane >> 4) & 1) * 8;
    const int bCh   = (lane >> 3) & 1;
    const int bRm   = bRow & 7;
    const int aRowByte[2] = {aRow * 128, (aRow + 16) * 128};
    const int bRowByte[4] = {bRow * 128, (bRow + 16) * 128,
                             (bRow + 32) * 128, (bRow + 48) * 128};

    float* rowScratch = reinterpret_cast<float*>(smem + SCRATCH_OFF);        // [2][128]
    float* colScratch = reinterpret_cast<float*>(smem + SCRATCH_OFF) + 256;  // [2][4][64]

    int tile = blockIdx.x;
    int bx, colTile; bool sym;
    decode_tile(tile, bx, colTile, sym);
    int rowBase = bx * BM, colBase = colTile * BN;

    int chunk = 0;
    load_stage(smem_u32, 0, rowBase, colBase, tid);
    CP_COMMIT();

    #pragma unroll 1
    while (true) {
        const int nxtTile = tile + GRID_GEMM;
        const bool hasNext = (nxtTile < NTILES);
        int nbx = 0, nct = 0; bool nsym = false;
        if (hasNext) decode_tile(nxtTile, nbx, nct, nsym);
        const int nRowBase = nbx * BM, nColBase = nct * BN;

        int acc[2][8][4];
        #pragma unroll
        for (int mt = 0; mt < 2; mt++)
            #pragma unroll
            for (int nt = 0; nt < 8; nt++)
                #pragma unroll
                for (int r = 0; r < 4; r++) acc[mt][nt][r] = 0;

        #pragma unroll 1
        for (int kt = 0; kt < NKT; kt++) {
            const uint32_t stage  = smem_u32 + (uint32_t)(chunk & 1) * STAGE_BYTES;
            const uint32_t nstage = smem_u32 + (uint32_t)((chunk + 1) & 1) * STAGE_BYTES;
            if (kt + 1 < NKT) {
                load_stage(nstage, kt + 1, rowBase, colBase, tid);
                CP_COMMIT(); CP_WAIT(1);
            } else if (hasNext) {
                load_stage(nstage, 0, nRowBase, nColBase, tid);
                CP_COMMIT(); CP_WAIT(1);
            } else {
                CP_WAIT(0);
            }
            __syncthreads();

            const uint32_t bBase = stage + 16384;
            #pragma unroll
            for (int s = 0; s < 4; s++) {
                uint32_t ah[2][4], bh[4][4];
                #pragma unroll
                for (int mt = 0; mt < 2; mt++)
                    ldsm4(ah[mt], swadr(stage, aRowByte[mt], aRm, 2 * s + aCh));
                #pragma unroll
                for (int p = 0; p < 4; p++)
                    ldsm4(bh[p], swadr(bBase, bRowByte[p], bRm, 2 * s + bCh));
                #pragma unroll
                for (int mt = 0; mt < 2; mt++)
                    #pragma unroll
                    for (int nt = 0; nt < 8; nt++)
                        imma16832(acc[mt][nt], ah[mt], bh[nt >> 1][(nt & 1) * 2],
                                  bh[nt >> 1][(nt & 1) * 2 + 1]);
            }
            __syncthreads();
            chunk++;
        }

        // ---------------- Epilogue (next tile's kt0 load is in flight) -------
        const float l2T = c_l2T;
        const int r8 = lane >> 2;
        float raL[4];
        #pragma unroll
        for (int mt = 0; mt < 2; mt++) {
            raL[mt * 2 + 0] = g_rs[rowBase + warpM * 32 + mt * 16 + 0 + r8] * l2T;
            raL[mt * 2 + 1] = g_rs[rowBase + warpM * 32 + mt * 16 + 8 + r8] * l2T;
        }
        float rbv[16];
        #pragma unroll
        for (int nt = 0; nt < 8; nt++) {
            const int c0 = colBase + warpN * 64 + nt * 8 + (lane & 3) * 2;
            rbv[nt * 2 + 0] = g_rs[c0];
            rbv[nt * 2 + 1] = g_rs[c0 + 1];
        }

        float rs0[2] = {0.0f, 0.0f}, rs1[2] = {0.0f, 0.0f};
        float cs[16];
        #pragma unroll
        for (int i = 0; i < 16; i++) cs[i] = 0.0f;

        #pragma unroll
        for (int mt = 0; mt < 2; mt++)
            #pragma unroll
            for (int nt = 0; nt < 8; nt++) {
                const float f0 = __int2float_rn(acc[mt][nt][0]);
                const float f1 = __int2float_rn(acc[mt][nt][1]);
                const float f2 = __int2float_rn(acc[mt][nt][2]);
                const float f3 = __int2float_rn(acc[mt][nt][3]);
                const float e0 = ex2(f0 * raL[mt * 2 + 0] * rbv[nt * 2 + 0]);
                const float e1 = ex2(f1 * raL[mt * 2 + 0] * rbv[nt * 2 + 1]);
                const float e2 = ex2(f2 * raL[mt * 2 + 1] * rbv[nt * 2 + 0]);
                const float e3 = ex2(f3 * raL[mt * 2 + 1] * rbv[nt * 2 + 1]);
                rs0[mt] += e0 + e1;
                rs1[mt] += e2 + e3;
                cs[nt * 2 + 0] += e0 + e2;
                cs[nt * 2 + 1] += e1 + e3;
            }

        #pragma unroll
        for (int off = 1; off <= 2; off <<= 1) {
            #pragma unroll
            for (int mt = 0; mt < 2; mt++) {
                rs0[mt] += __shfl_xor_sync(0xffffffffu, rs0[mt], off);
                rs1[mt] += __shfl_xor_sync(0xffffffffu, rs1[mt], off);
            }
        }
        if ((lane & 3) == 0) {
            #pragma unroll
            for (int mt = 0; mt < 2; mt++) {
                rowScratch[warpN * 128 + warpM * 32 + mt * 16 + 0 + r8] = rs0[mt];
                rowScratch[warpN * 128 + warpM * 32 + mt * 16 + 8 + r8] = rs1[mt];
            }
        }
        if (sym) {
            #pragma unroll
            for (int i = 0; i < 16; i++) {
                #pragma unroll
                for (int off = 4; off <= 16; off <<= 1)
                    cs[i] += __shfl_xor_sync(0xffffffffu, cs[i], off);
            }
            if (lane < 4) {
                #pragma unroll
                for (int nt = 0; nt < 8; nt++) {
                    colScratch[(warpN * 4 + warpM) * 64 + nt * 8 + lane * 2 + 0] = cs[nt * 2 + 0];
                    colScratch[(warpN * 4 + warpM) * 64 + nt * 8 + lane * 2 + 1] = cs[nt * 2 + 1];
                }
            }
        }
        __syncthreads();

        if (tid < 128) {
            const float p = rowScratch[tid] + rowScratch[128 + tid];
            g_partial[(size_t)(rowBase + tid) * NCOLTILES + colTile] = p;
            if (sym) {
                const int wn = tid >> 6, ix = tid & 63;
                float c = colScratch[(wn * 4 + 0) * 64 + ix] + colScratch[(wn * 4 + 1) * 64 + ix]
                        + colScratch[(wn * 4 + 2) * 64 + ix] + colScratch[(wn * 4 + 3) * 64 + ix];
                g_partial[(size_t)(colBase + tid) * NCOLTILES + bx] = c;
            }
        }
        __syncthreads();   // scratch reuse safety for next tile

        if (!hasNext) break;
        tile = nxtTile; bx = nbx; colTile = nct; sym = nsym;
        rowBase = nRowBase; colBase = nColBase;
    }
}

// ---------------------------------------------------------------------------
// Kernel 3: per-row loss + grid-wide mean (last-block pattern, deterministic).
// Partials loaded as float2 (one 8B load per lane). dp4a correction terms on
// the SAME int8 data the GEMM consumed; diagonal replaced by exact exp(1/T).
// ---------------------------------------------------------------------------
__global__ void __launch_bounds__(256) loss_reduce_kernel(float* __restrict__ out) {
    __shared__ float warpLoss[8];
    __shared__ int   isLast;
    const int bid  = blockIdx.x;
    const int row  = bid * 8 + (threadIdx.x >> 5);
    const int lane = threadIdx.x & 31;

    const float2 tp = reinterpret_cast<const float2*>(g_partial + (size_t)row * NCOLTILES)[lane];
    float total = tp.x + tp.y;

    const uint2 qa = reinterpret_cast<const uint2*>(g_q + (size_t)row * D)[lane];
    const uint2 qb = reinterpret_cast<const uint2*>(g_q + (size_t)(N_ROWS + row) * D)[lane];
    const uint2 qc = reinterpret_cast<const uint2*>(g_q + (size_t)N_ROWS * D)[lane];

    int dpi = __dp4a((int)qa.x, (int)qb.x, 0); dpi = __dp4a((int)qa.y, (int)qb.y, dpi);
    int d0i = __dp4a((int)qa.x, (int)qc.x, 0); d0i = __dp4a((int)qa.y, (int)qc.y, d0i);
    int dii = __dp4a((int)qa.x, (int)qa.x, 0); dii = __dp4a((int)qa.y, (int)qa.y, dii);

    #pragma unroll
    for (int off = 16; off > 0; off >>= 1) {
        total += __shfl_xor_sync(0xffffffffu, total, off);
        dpi   += __shfl_xor_sync(0xffffffffu, dpi, off);
        d0i   += __shfl_xor_sync(0xffffffffu, d0i, off);
        dii   += __shfl_xor_sync(0xffffffffu, dii, off);
    }
    if (lane == 0) {
        const float ra = g_rs[row];
        const float rb = g_rs[N_ROWS + row];
        const float rc = g_rs[N_ROWS];
        const float dp    = __int2float_rn(dpi) * ra * rb;
        const float d0    = __int2float_rn(d0i) * ra * rc;
        const float dii_f = __int2float_rn(dii) * ra * ra;
        float sum_negs = total - ex2(d0 * c_l2T) - ex2(dii_f * c_l2T) + ex2(c_l2T);
        warpLoss[threadIdx.x >> 5] = logf(sum_negs) - dp * c_invT;
    }
    __syncthreads();

    if (threadIdx.x == 0) {
        float bs = 0.0f;
        #pragma unroll
        for (int i = 0; i < 8; i++) bs += warpLoss[i];
        g_blocksum[bid] = bs;
        __threadfence();
        int old = atomicAdd(&g_counter, 1);
        isLast = (old == NLOSSBLK - 1);
    }
    __syncthreads();

    if (isLast) {
        __shared__ float s[256];
        float v = 0.0f;
        #pragma unroll
        for (int h = 0; h < 2; h++) {
            float t;
            asm volatile("ld.global.cg.f32 %0, [%1];" : "=f"(t)
                         : "l"(g_blocksum + threadIdx.x + h * 256));
            v += t;
        }
        s[threadIdx.x] = v;
        __syncthreads();
        #pragma unroll
        for (int stride = 128; stride > 0; stride >>= 1) {
            if (threadIdx.x < stride) s[threadIdx.x] += s[threadIdx.x + stride];
            __syncthreads();
        }
        if (threadIdx.x == 0) {
            out[0] = s[0] * (1.0f / N_ROWS);
            g_counter = 0;   // reset for graph replay
        }
    }
}

// ---------------------------------------------------------------------------
extern "C" void kernel_launch(void* const* d_in, const int* in_sizes, int n_in,
                              void* d_out, int out_size) {
    const float* z1 = (const float*)d_in[0];
    const float* z2 = (const float*)d_in[1];
    float* out = (float*)d_out;

    cudaFuncSetAttribute(simsum_mma_kernel,
                         cudaFuncAttributeMaxDynamicSharedMemorySize, SMEM_TOTAL);

    normalize_kernel<<<TWO_N / 32, 256>>>(z1, z2);
    simsum_mma_kernel<<<GRID_GEMM, 256, SMEM_TOTAL>>>();
    loss_reduce_kernel<<<NLOSSBLK, 256>>>(out);
}

// round 16
// speedup vs baseline: 1.1747x; 1.0568x over previous
#include <cuda_runtime.h>
#include <cuda_bf16.h>
#include <math.h>
#include <stdint.h>

#define N_ROWS 4096
#define D      256
#define TWO_N  8192
#define BM 128
#define BN 128
#define BK 128                     // int8 elements per k-chunk (128 bytes/row)
#define NKT (D / BK)               // 2 k-chunks
#define NCOLTILES 64
#define NLOSSBLK (N_ROWS / 8)      // 512 loss blocks
#define NTILES 1552
#define GRID_GEMM 296              // 2 CTAs per SM, persistent

// exp(x/T) = 2^(x * invT * log2(e))
__device__ __constant__ float c_l2T  = 20.609929f;
__device__ __constant__ float c_invT = 14.285714285714286f;

// Scratch (device globals; no allocation anywhere)
__device__ int8_t  g_q[TWO_N * D];       // int8 quantized normalized rows
__device__ float   g_rs[TWO_N];          // per-row dequant scale (absmax/127)
__device__ float   g_partial[N_ROWS * NCOLTILES];
__device__ float   g_blocksum[NLOSSBLK];
__device__ int     g_counter = 0;        // loss last-block counter

// ---------------------------------------------------------------------------
// PTX helpers (sm_80+ baseline; PDL intrinsics are sm_90+, target is sm_100)
// ---------------------------------------------------------------------------
__device__ __forceinline__ uint32_t smem_to_u32(const void* p) {
    uint32_t a;
    asm("{ .reg .u64 t; cvta.to.shared.u64 t, %1; cvt.u32.u64 %0, t; }" : "=r"(a) : "l"(p));
    return a;
}
__device__ __forceinline__ float ex2(float x) {
    float r;
    asm("ex2.approx.ftz.f32 %0, %1;" : "=f"(r) : "f"(x));
    return r;
}
#define CP_ASYNC16(dst, src) \
    asm volatile("cp.async.cg.shared.global [%0], [%1], 16;" :: "r"(dst), "l"(src))
#define CP_COMMIT() asm volatile("cp.async.commit_group;" ::: "memory")
#define CP_WAIT(n)  asm volatile("cp.async.wait_group %0;" :: "n"(n) : "memory")

__device__ __forceinline__ void ldsm4(uint32_t* r, uint32_t addr) {
    asm volatile("ldmatrix.sync.aligned.m8n8.x4.shared.b16 {%0,%1,%2,%3}, [%4];"
        : "=r"(r[0]), "=r"(r[1]), "=r"(r[2]), "=r"(r[3]) : "r"(addr));
}
// s8 IMMA: D(s32) = A(s8 16x32) * B(s8 32x8) + D
__device__ __forceinline__ void imma16832(int* c, const uint32_t* a,
                                          uint32_t b0, uint32_t b1) {
    asm volatile("mma.sync.aligned.m16n8k32.row.col.s32.s8.s8.s32 "
        "{%0,%1,%2,%3}, {%4,%5,%6,%7}, {%8,%9}, {%0,%1,%2,%3};"
        : "+r"(c[0]), "+r"(c[1]), "+r"(c[2]), "+r"(c[3])
        : "r"(a[0]), "r"(a[1]), "r"(a[2]), "r"(a[3]), "r"(b0), "r"(b1));
}

__device__ __forceinline__ uint32_t swadr(uint32_t base, int rowByte, int rm, int ch) {
    return base + rowByte + ((ch ^ rm) << 4);
}

#define STAGE_BYTES 32768
#define SCRATCH_OFF (2 * STAGE_BYTES)            // 65536: epilogue scratch
#define SMEM_TOTAL  (SCRATCH_OFF + 3072)         // 68608 B (2 CTAs/SM fits)

// ---------------------------------------------------------------------------
// Kernel 1: L2-normalize rows -> int8 (per-row absmax quant) + scale.
// One warp per row (R12 config: grid 1024, best measured occupancy).
// ---------------------------------------------------------------------------
__global__ void __launch_bounds__(256) normalize_kernel(const float* __restrict__ z1,
                                                        const float* __restrict__ z2) {
    const int row  = blockIdx.x * 8 + (threadIdx.x >> 5);
    const int lane = threadIdx.x & 31;
    const float* src = (row < N_ROWS) ? (z1 + (size_t)row * D)
                                      : (z2 + (size_t)(row - N_ROWS) * D);
    float4 a = reinterpret_cast<const float4*>(src)[lane];
    float4 b = reinterpret_cast<const float4*>(src)[lane + 32];
    float ss = a.x*a.x + a.y*a.y + a.z*a.z + a.w*a.w
             + b.x*b.x + b.y*b.y + b.z*b.z + b.w*b.w;
    #pragma unroll
    for (int off = 16; off > 0; off >>= 1)
        ss += __shfl_xor_sync(0xffffffffu, ss, off);
    const float scale = 1.0f / fmaxf(sqrtf(ss), 1e-12f);

    float v[8] = {a.x*scale, a.y*scale, a.z*scale, a.w*scale,
                  b.x*scale, b.y*scale, b.z*scale, b.w*scale};
    float m = 0.0f;
    #pragma unroll
    for (int i = 0; i < 8; i++) m = fmaxf(m, fabsf(v[i]));
    #pragma unroll
    for (int off = 16; off > 0; off >>= 1)
        m = fmaxf(m, __shfl_xor_sync(0xffffffffu, m, off));

    const float qs = 127.0f / m;
    int q[8];
    #pragma unroll
    for (int i = 0; i < 8; i++) q[i] = __float2int_rn(v[i] * qs);

    uint32_t w0 = (q[0] & 255) | ((q[1] & 255) << 8) | ((q[2] & 255) << 16) | (q[3] << 24);
    uint32_t w1 = (q[4] & 255) | ((q[5] & 255) << 8) | ((q[6] & 255) << 16) | (q[7] << 24);
    uint32_t* dst = reinterpret_cast<uint32_t*>(g_q + (size_t)row * D);
    dst[lane]      = w0;        // elements 4*lane .. 4*lane+3
    dst[lane + 32] = w1;        // elements 128+4*lane ..
    if (lane == 0) g_rs[row] = m * (1.0f / 127.0f);
}

// ---------------------------------------------------------------------------
// Stage loader: A 128x128B (region 0) + B 128x128B (region +16384).
// 2048 16B chunks, 8 per thread.
// ---------------------------------------------------------------------------
__device__ __forceinline__ void load_stage(uint32_t stageAddr, int kt,
                                           int rowBase, int colBase, int tid) {
    const int kOff = kt * BK;
    #pragma unroll
    for (int i = 0; i < 8; i++) {
        const int v = i * 256 + tid;              // 0..2047
        const int half = v >> 10;                 // 0 = A, 1 = B
        const int r = (v >> 3) & 127, c = v & 7;
        const int gRow = half ? (colBase + r) : (rowBase + r);
        const void* src = g_q + (size_t)gRow * D + kOff + c * 16;
        const uint32_t dst = stageAddr + half * 16384 + r * 128 + ((c ^ (r & 7)) << 4);
        CP_ASYNC16(dst, src);
    }
}

// Tile decode: b<1024 -> right half (bx=b>>5, ct=32+(b&31)); else triangular.
__device__ __forceinline__ void decode_tile(int b, int& bx, int& ct, bool& sym) {
    if (b < 1024) {
        bx = b >> 5; ct = 32 + (b & 31); sym = false;
    } else {
        const int t = b - 1024;
        int e = (int)((sqrtf(8.0f * t + 1.0f) - 1.0f) * 0.5f);
        while ((e + 1) * (e + 2) / 2 <= t) e++;
        while (e * (e + 1) / 2 > t) e--;
        bx = e; ct = t - e * (e + 1) / 2; sym = (ct != bx);
    }
}

// ---------------------------------------------------------------------------
// Kernel 2: persistent INT8-IMMA fused sim-GEMM + dequant + exp + row/col
// sums. R12 verbatim, PLUS PDL: launched overlapping normalize_kernel; all
// per-thread index setup and tile decode run during the overlap, then
// cudaGridDependencySynchronize() gates the first read of g_q.
// ---------------------------------------------------------------------------
__global__ void __launch_bounds__(256, 2) simsum_mma_kernel() {
    extern __shared__ char smem[];
    const uint32_t smem_u32 = smem_to_u32(smem);
    const int tid = threadIdx.x;

    const int lane  = tid & 31;
    const int w     = tid >> 5;
    const int warpM = w >> 1;
    const int warpN = w & 1;

    const int aRow  = warpM * 32 + (lane & 7) + ((lane >> 3) & 1) * 8;
    const int aCh   = (lane >> 4) & 1;
    const int aRm   = aRow & 7;
    const int bRow  = warpN * 64 + (lane & 7) + ((lane >> 4) & 1) * 8;
    const int bCh   = (lane >> 3) & 1;
    const int bRm   = bRow & 7;
    const int aRowByte[2] = {aRow * 128, (aRow + 16) * 128};
    const int bRowByte[4] = {bRow * 128, (bRow + 16) * 128,
                             (bRow + 32) * 128, (bRow + 48) * 128};

    float* rowScratch = reinterpret_cast<float*>(smem + SCRATCH_OFF);        // [2][128]
    float* colScratch = reinterpret_cast<float*>(smem + SCRATCH_OFF) + 256;  // [2][4][64]

    int tile = blockIdx.x;
    int bx, colTile; bool sym;
    decode_tile(tile, bx, colTile, sym);
    int rowBase = bx * BM, colBase = colTile * BN;

    // PDL gate: normalize_kernel must be complete before reading g_q/g_rs.
    cudaGridDependencySynchronize();

    int chunk = 0;
    load_stage(smem_u32, 0, rowBase, colBase, tid);
    CP_COMMIT();

    #pragma unroll 1
    while (true) {
        const int nxtTile = tile + GRID_GEMM;
        const bool hasNext = (nxtTile < NTILES);
        int nbx = 0, nct = 0; bool nsym = false;
        if (hasNext) decode_tile(nxtTile, nbx, nct, nsym);
        const int nRowBase = nbx * BM, nColBase = nct * BN;

        int acc[2][8][4];
        #pragma unroll
        for (int mt = 0; mt < 2; mt++)
            #pragma unroll
            for (int nt = 0; nt < 8; nt++)
                #pragma unroll
                for (int r = 0; r < 4; r++) acc[mt][nt][r] = 0;

        #pragma unroll 1
        for (int kt = 0; kt < NKT; kt++) {
            const uint32_t stage  = smem_u32 + (uint32_t)(chunk & 1) * STAGE_BYTES;
            const uint32_t nstage = smem_u32 + (uint32_t)((chunk + 1) & 1) * STAGE_BYTES;
            if (kt + 1 < NKT) {
                load_stage(nstage, kt + 1, rowBase, colBase, tid);
                CP_COMMIT(); CP_WAIT(1);
            } else if (hasNext) {
                load_stage(nstage, 0, nRowBase, nColBase, tid);
                CP_COMMIT(); CP_WAIT(1);
            } else {
                CP_WAIT(0);
            }
            __syncthreads();

            const uint32_t bBase = stage + 16384;
            #pragma unroll
            for (int s = 0; s < 4; s++) {
                uint32_t ah[2][4], bh[4][4];
                #pragma unroll
                for (int mt = 0; mt < 2; mt++)
                    ldsm4(ah[mt], swadr(stage, aRowByte[mt], aRm, 2 * s + aCh));
                #pragma unroll
                for (int p = 0; p < 4; p++)
                    ldsm4(bh[p], swadr(bBase, bRowByte[p], bRm, 2 * s + bCh));
                #pragma unroll
                for (int mt = 0; mt < 2; mt++)
                    #pragma unroll
                    for (int nt = 0; nt < 8; nt++)
                        imma16832(acc[mt][nt], ah[mt], bh[nt >> 1][(nt & 1) * 2],
                                  bh[nt >> 1][(nt & 1) * 2 + 1]);
            }
            __syncthreads();
            chunk++;
        }

        // ---------------- Epilogue (next tile's kt0 load is in flight) -------
        const float l2T = c_l2T;
        const int r8 = lane >> 2;
        float raL[4];
        #pragma unroll
        for (int mt = 0; mt < 2; mt++) {
            raL[mt * 2 + 0] = g_rs[rowBase + warpM * 32 + mt * 16 + 0 + r8] * l2T;
            raL[mt * 2 + 1] = g_rs[rowBase + warpM * 32 + mt * 16 + 8 + r8] * l2T;
        }
        float rbv[16];
        #pragma unroll
        for (int nt = 0; nt < 8; nt++) {
            const int c0 = colBase + warpN * 64 + nt * 8 + (lane & 3) * 2;
            rbv[nt * 2 + 0] = g_rs[c0];
            rbv[nt * 2 + 1] = g_rs[c0 + 1];
        }

        float rs0[2] = {0.0f, 0.0f}, rs1[2] = {0.0f, 0.0f};
        float cs[16];
        #pragma unroll
        for (int i = 0; i < 16; i++) cs[i] = 0.0f;

        #pragma unroll
        for (int mt = 0; mt < 2; mt++)
            #pragma unroll
            for (int nt = 0; nt < 8; nt++) {
                const float f0 = __int2float_rn(acc[mt][nt][0]);
                const float f1 = __int2float_rn(acc[mt][nt][1]);
                const float f2 = __int2float_rn(acc[mt][nt][2]);
                const float f3 = __int2float_rn(acc[mt][nt][3]);
                const float e0 = ex2(f0 * raL[mt * 2 + 0] * rbv[nt * 2 + 0]);
                const float e1 = ex2(f1 * raL[mt * 2 + 0] * rbv[nt * 2 + 1]);
                const float e2 = ex2(f2 * raL[mt * 2 + 1] * rbv[nt * 2 + 0]);
                const float e3 = ex2(f3 * raL[mt * 2 + 1] * rbv[nt * 2 + 1]);
                rs0[mt] += e0 + e1;
                rs1[mt] += e2 + e3;
                cs[nt * 2 + 0] += e0 + e2;
                cs[nt * 2 + 1] += e1 + e3;
            }

        #pragma unroll
        for (int off = 1; off <= 2; off <<= 1) {
            #pragma unroll
            for (int mt = 0; mt < 2; mt++) {
                rs0[mt] += __shfl_xor_sync(0xffffffffu, rs0[mt], off);
                rs1[mt] += __shfl_xor_sync(0xffffffffu, rs1[mt], off);
            }
        }
        if ((lane & 3) == 0) {
            #pragma unroll
            for (int mt = 0; mt < 2; mt++) {
                rowScratch[warpN * 128 + warpM * 32 + mt * 16 + 0 + r8] = rs0[mt];
                rowScratch[warpN * 128 + warpM * 32 + mt * 16 + 8 + r8] = rs1[mt];
            }
        }
        if (sym) {
            #pragma unroll
            for (int i = 0; i < 16; i++) {
                #pragma unroll
                for (int off = 4; off <= 16; off <<= 1)
                    cs[i] += __shfl_xor_sync(0xffffffffu, cs[i], off);
            }
            if (lane < 4) {
                #pragma unroll
                for (int nt = 0; nt < 8; nt++) {
                    colScratch[(warpN * 4 + warpM) * 64 + nt * 8 + lane * 2 + 0] = cs[nt * 2 + 0];
                    colScratch[(warpN * 4 + warpM) * 64 + nt * 8 + lane * 2 + 1] = cs[nt * 2 + 1];
                }
            }
        }
        __syncthreads();

        if (tid < 128) {
            const float p = rowScratch[tid] + rowScratch[128 + tid];
            g_partial[(size_t)(rowBase + tid) * NCOLTILES + colTile] = p;
            if (sym) {
                const int wn = tid >> 6, ix = tid & 63;
                float c = colScratch[(wn * 4 + 0) * 64 + ix] + colScratch[(wn * 4 + 1) * 64 + ix]
                        + colScratch[(wn * 4 + 2) * 64 + ix] + colScratch[(wn * 4 + 3) * 64 + ix];
                g_partial[(size_t)(colBase + tid) * NCOLTILES + bx] = c;
            }
        }
        __syncthreads();   // scratch reuse safety for next tile

        if (!hasNext) break;
        tile = nxtTile; bx = nbx; colTile = nct; sym = nsym;
        rowBase = nRowBase; colBase = nColBase;
    }
}

// ---------------------------------------------------------------------------
// Kernel 3: per-row loss + grid-wide mean (last-block pattern, deterministic).
// R12 verbatim + PDL gate before reading g_partial.
// ---------------------------------------------------------------------------
__global__ void __launch_bounds__(256) loss_reduce_kernel(float* __restrict__ out) {
    __shared__ float warpLoss[8];
    __shared__ int   isLast;
    const int bid  = blockIdx.x;
    const int row  = bid * 8 + (threadIdx.x >> 5);
    const int lane = threadIdx.x & 31;

    // PDL gate: simsum_mma_kernel must be complete before reading g_partial.
    cudaGridDependencySynchronize();

    float total = g_partial[(size_t)row * NCOLTILES + lane]
                + g_partial[(size_t)row * NCOLTILES + lane + 32];

    const uint2 qa = reinterpret_cast<const uint2*>(g_q + (size_t)row * D)[lane];
    const uint2 qb = reinterpret_cast<const uint2*>(g_q + (size_t)(N_ROWS + row) * D)[lane];
    const uint2 qc = reinterpret_cast<const uint2*>(g_q + (size_t)N_ROWS * D)[lane];

    int dpi = __dp4a((int)qa.x, (int)qb.x, 0); dpi = __dp4a((int)qa.y, (int)qb.y, dpi);
    int d0i = __dp4a((int)qa.x, (int)qc.x, 0); d0i = __dp4a((int)qa.y, (int)qc.y, d0i);
    int dii = __dp4a((int)qa.x, (int)qa.x, 0); dii = __dp4a((int)qa.y, (int)qa.y, dii);

    #pragma unroll
    for (int off = 16; off > 0; off >>= 1) {
        total += __shfl_xor_sync(0xffffffffu, total, off);
        dpi   += __shfl_xor_sync(0xffffffffu, dpi, off);
        d0i   += __shfl_xor_sync(0xffffffffu, d0i, off);
        dii   += __shfl_xor_sync(0xffffffffu, dii, off);
    }
    if (lane == 0) {
        const float ra = g_rs[row];
        const float rb = g_rs[N_ROWS + row];
        const float rc = g_rs[N_ROWS];
        const float dp    = __int2float_rn(dpi) * ra * rb;
        const float d0    = __int2float_rn(d0i) * ra * rc;
        const float dii_f = __int2float_rn(dii) * ra * ra;
        float sum_negs = total - ex2(d0 * c_l2T) - ex2(dii_f * c_l2T) + ex2(c_l2T);
        warpLoss[threadIdx.x >> 5] = logf(sum_negs) - dp * c_invT;
    }
    __syncthreads();

    if (threadIdx.x == 0) {
        float bs = 0.0f;
        #pragma unroll
        for (int i = 0; i < 8; i++) bs += warpLoss[i];
        g_blocksum[bid] = bs;
        __threadfence();
        int old = atomicAdd(&g_counter, 1);
        isLast = (old == NLOSSBLK - 1);
    }
    __syncthreads();

    if (isLast) {
        __shared__ float s[256];
        float v = 0.0f;
        #pragma unroll
        for (int h = 0; h < 2; h++) {
            float t;
            asm volatile("ld.global.cg.f32 %0, [%1];" : "=f"(t)
                         : "l"(g_blocksum + threadIdx.x + h * 256));
            v += t;
        }
        s[threadIdx.x] = v;
        __syncthreads();
        #pragma unroll
        for (int stride = 128; stride > 0; stride >>= 1) {
            if (threadIdx.x < stride) s[threadIdx.x] += s[threadIdx.x + stride];
            __syncthreads();
        }
        if (threadIdx.x == 0) {
            out[0] = s[0] * (1.0f / N_ROWS);
            g_counter = 0;   // reset for graph replay
        }
    }
}

// ---------------------------------------------------------------------------
extern "C" void kernel_launch(void* const* d_in, const int* in_sizes, int n_in,
                              void* d_out, int out_size) {
    const float* z1 = (const float*)d_in[0];
    const float* z2 = (const float*)d_in[1];
    float* out = (float*)d_out;

    cudaFuncSetAttribute(simsum_mma_kernel,
                         cudaFuncAttributeMaxDynamicSharedMemorySize, SMEM_TOTAL);

    normalize_kernel<<<TWO_N / 8, 256>>>(z1, z2);

    // PDL launches: overlap dependent kernel prologue with predecessor tail.
    cudaLaunchAttribute attr[1];
    attr[0].id = cudaLaunchAttributeProgrammaticStreamSerialization;
    attr[0].val.programmaticStreamSerializationAllowed = 1;

    {
        cudaLaunchConfig_t cfg = {};
        cfg.gridDim = dim3(GRID_GEMM, 1, 1);
        cfg.blockDim = dim3(256, 1, 1);
        cfg.dynamicSmemBytes = SMEM_TOTAL;
        cfg.attrs = attr;
        cfg.numAttrs = 1;
        cudaLaunchKernelEx(&cfg, simsum_mma_kernel);
    }
    {
        cudaLaunchConfig_t cfg = {};
        cfg.gridDim = dim3(NLOSSBLK, 1, 1);
        cfg.blockDim = dim3(256, 1, 1);
        cfg.dynamicSmemBytes = 0;
        cfg.attrs = attr;
        cfg.numAttrs = 1;
        cudaLaunchKernelEx(&cfg, loss_reduce_kernel, out);
    }
}

// round 17
// speedup vs baseline: 1.1807x; 1.0051x over previous
#include <cuda_runtime.h>
#include <cuda_bf16.h>
#include <math.h>
#include <stdint.h>

#define N_ROWS 4096
#define D      256
#define TWO_N  8192
#define BM 128
#define BN 128
#define BK 128                     // int8 elements per k-chunk (128 bytes/row)
#define NKT (D / BK)               // 2 k-chunks
#define NCOLTILES 64
#define NLOSSBLK (N_ROWS / 8)      // 512 loss blocks
#define NTILES 1552
#define GRID_GEMM 296              // 2 CTAs per SM, persistent

// exp(x/T) = 2^(x * invT * log2(e))
__device__ __constant__ float c_l2T  = 20.609929f;
__device__ __constant__ float c_invT = 14.285714285714286f;

// Scratch (device globals; no allocation anywhere)
__device__ int8_t  g_q[TWO_N * D];       // int8 quantized normalized rows
__device__ float   g_rs[TWO_N];          // per-row dequant scale (absmax/127)
__device__ float   g_partial[N_ROWS * NCOLTILES];
__device__ float   g_blocksum[NLOSSBLK];
__device__ int     g_counter = 0;        // loss last-block counter

// ---------------------------------------------------------------------------
// PTX helpers (sm_80+ baseline; PDL intrinsics are sm_90+, target is sm_100)
// ---------------------------------------------------------------------------
__device__ __forceinline__ uint32_t smem_to_u32(const void* p) {
    uint32_t a;
    asm("{ .reg .u64 t; cvta.to.shared.u64 t, %1; cvt.u32.u64 %0, t; }" : "=r"(a) : "l"(p));
    return a;
}
__device__ __forceinline__ float ex2(float x) {
    float r;
    asm("ex2.approx.ftz.f32 %0, %1;" : "=f"(r) : "f"(x));
    return r;
}
#define CP_ASYNC16(dst, src) \
    asm volatile("cp.async.cg.shared.global [%0], [%1], 16;" :: "r"(dst), "l"(src))
#define CP_COMMIT() asm volatile("cp.async.commit_group;" ::: "memory")
#define CP_WAIT(n)  asm volatile("cp.async.wait_group %0;" :: "n"(n) : "memory")

__device__ __forceinline__ void ldsm4(uint32_t* r, uint32_t addr) {
    asm volatile("ldmatrix.sync.aligned.m8n8.x4.shared.b16 {%0,%1,%2,%3}, [%4];"
        : "=r"(r[0]), "=r"(r[1]), "=r"(r[2]), "=r"(r[3]) : "r"(addr));
}
// s8 IMMA: D(s32) = A(s8 16x32) * B(s8 32x8) + D
__device__ __forceinline__ void imma16832(int* c, const uint32_t* a,
                                          uint32_t b0, uint32_t b1) {
    asm volatile("mma.sync.aligned.m16n8k32.row.col.s32.s8.s8.s32 "
        "{%0,%1,%2,%3}, {%4,%5,%6,%7}, {%8,%9}, {%0,%1,%2,%3};"
        : "+r"(c[0]), "+r"(c[1]), "+r"(c[2]), "+r"(c[3])
        : "r"(a[0]), "r"(a[1]), "r"(a[2]), "r"(a[3]), "r"(b0), "r"(b1));
}

__device__ __forceinline__ uint32_t swadr(uint32_t base, int rowByte, int rm, int ch) {
    return base + rowByte + ((ch ^ rm) << 4);
}

#define STAGE_BYTES 32768
#define SCRATCH_OFF (2 * STAGE_BYTES)            // 65536: epilogue scratch
#define SMEM_TOTAL  (SCRATCH_OFF + 3072)         // 68608 B (2 CTAs/SM fits)

// ---------------------------------------------------------------------------
// Kernel 1: L2-normalize rows -> int8 (per-row absmax quant) + scale.
// One warp per row. ss and absmax reductions INTERLEAVED in one 5-step pass
// (absmax over raw values; m = amax_raw * scale since scale > 0).
// ---------------------------------------------------------------------------
__global__ void __launch_bounds__(256) normalize_kernel(const float* __restrict__ z1,
                                                        const float* __restrict__ z2) {
    const int row  = blockIdx.x * 8 + (threadIdx.x >> 5);
    const int lane = threadIdx.x & 31;
    const float* src = (row < N_ROWS) ? (z1 + (size_t)row * D)
                                      : (z2 + (size_t)(row - N_ROWS) * D);
    float4 a = reinterpret_cast<const float4*>(src)[lane];
    float4 b = reinterpret_cast<const float4*>(src)[lane + 32];

    float ss = a.x*a.x + a.y*a.y + a.z*a.z + a.w*a.w
             + b.x*b.x + b.y*b.y + b.z*b.z + b.w*b.w;
    float am = fmaxf(fmaxf(fmaxf(fabsf(a.x), fabsf(a.y)), fmaxf(fabsf(a.z), fabsf(a.w))),
                     fmaxf(fmaxf(fabsf(b.x), fabsf(b.y)), fmaxf(fabsf(b.z), fabsf(b.w))));
    #pragma unroll
    for (int off = 16; off > 0; off >>= 1) {
        ss += __shfl_xor_sync(0xffffffffu, ss, off);
        am  = fmaxf(am, __shfl_xor_sync(0xffffffffu, am, off));
    }
    const float scale = 1.0f / fmaxf(sqrtf(ss), 1e-12f);
    const float m  = am * scale;           // = max|v_i| exactly up to 1 ulp
    const float qs = 127.0f / m;

    float v[8] = {a.x*scale, a.y*scale, a.z*scale, a.w*scale,
                  b.x*scale, b.y*scale, b.z*scale, b.w*scale};
    int q[8];
    #pragma unroll
    for (int i = 0; i < 8; i++) q[i] = __float2int_rn(v[i] * qs);

    uint32_t w0 = (q[0] & 255) | ((q[1] & 255) << 8) | ((q[2] & 255) << 16) | (q[3] << 24);
    uint32_t w1 = (q[4] & 255) | ((q[5] & 255) << 8) | ((q[6] & 255) << 16) | (q[7] << 24);
    uint32_t* dst = reinterpret_cast<uint32_t*>(g_q + (size_t)row * D);
    dst[lane]      = w0;        // elements 4*lane .. 4*lane+3
    dst[lane + 32] = w1;        // elements 128+4*lane ..
    if (lane == 0) g_rs[row] = m * (1.0f / 127.0f);
}

// ---------------------------------------------------------------------------
// Stage loader: A 128x128B (region 0) + B 128x128B (region +16384).
// 2048 16B chunks, 8 per thread.
// ---------------------------------------------------------------------------
__device__ __forceinline__ void load_stage(uint32_t stageAddr, int kt,
                                           int rowBase, int colBase, int tid) {
    const int kOff = kt * BK;
    #pragma unroll
    for (int i = 0; i < 8; i++) {
        const int v = i * 256 + tid;              // 0..2047
        const int half = v >> 10;                 // 0 = A, 1 = B
        const int r = (v >> 3) & 127, c = v & 7;
        const int gRow = half ? (colBase + r) : (rowBase + r);
        const void* src = g_q + (size_t)gRow * D + kOff + c * 16;
        const uint32_t dst = stageAddr + half * 16384 + r * 128 + ((c ^ (r & 7)) << 4);
        CP_ASYNC16(dst, src);
    }
}

// Tile decode: b<1024 -> right half (bx=b>>5, ct=32+(b&31)); else triangular.
__device__ __forceinline__ void decode_tile(int b, int& bx, int& ct, bool& sym) {
    if (b < 1024) {
        bx = b >> 5; ct = 32 + (b & 31); sym = false;
    } else {
        const int t = b - 1024;
        int e = (int)((sqrtf(8.0f * t + 1.0f) - 1.0f) * 0.5f);
        while ((e + 1) * (e + 2) / 2 <= t) e++;
        while (e * (e + 1) / 2 > t) e--;
        bx = e; ct = t - e * (e + 1) / 2; sym = (ct != bx);
    }
}

// ---------------------------------------------------------------------------
// Kernel 2: persistent INT8-IMMA fused sim-GEMM + dequant + exp + row/col
// sums. R16 verbatim (PDL-gated; static schedule; 2-stage cp.async).
// ---------------------------------------------------------------------------
__global__ void __launch_bounds__(256, 2) simsum_mma_kernel() {
    extern __shared__ char smem[];
    const uint32_t smem_u32 = smem_to_u32(smem);
    const int tid = threadIdx.x;

    const int lane  = tid & 31;
    const int w     = tid >> 5;
    const int warpM = w >> 1;
    const int warpN = w & 1;

    const int aRow  = warpM * 32 + (lane & 7) + ((lane >> 3) & 1) * 8;
    const int aCh   = (lane >> 4) & 1;
    const int aRm   = aRow & 7;
    const int bRow  = warpN * 64 + (lane & 7) + ((lane >> 4) & 1) * 8;
    const int bCh   = (lane >> 3) & 1;
    const int bRm   = bRow & 7;
    const int aRowByte[2] = {aRow * 128, (aRow + 16) * 128};
    const int bRowByte[4] = {bRow * 128, (bRow + 16) * 128,
                             (bRow + 32) * 128, (bRow + 48) * 128};

    float* rowScratch = reinterpret_cast<float*>(smem + SCRATCH_OFF);        // [2][128]
    float* colScratch = reinterpret_cast<float*>(smem + SCRATCH_OFF) + 256;  // [2][4][64]

    int tile = blockIdx.x;
    int bx, colTile; bool sym;
    decode_tile(tile, bx, colTile, sym);
    int rowBase = bx * BM, colBase = colTile * BN;

    // PDL gate: normalize_kernel must be complete before reading g_q/g_rs.
    cudaGridDependencySynchronize();

    int chunk = 0;
    load_stage(smem_u32, 0, rowBase, colBase, tid);
    CP_COMMIT();

    #pragma unroll 1
    while (true) {
        const int nxtTile = tile + GRID_GEMM;
        const bool hasNext = (nxtTile < NTILES);
        int nbx = 0, nct = 0; bool nsym = false;
        if (hasNext) decode_tile(nxtTile, nbx, nct, nsym);
        const int nRowBase = nbx * BM, nColBase = nct * BN;

        int acc[2][8][4];
        #pragma unroll
        for (int mt = 0; mt < 2; mt++)
            #pragma unroll
            for (int nt = 0; nt < 8; nt++)
                #pragma unroll
                for (int r = 0; r < 4; r++) acc[mt][nt][r] = 0;

        #pragma unroll 1
        for (int kt = 0; kt < NKT; kt++) {
            const uint32_t stage  = smem_u32 + (uint32_t)(chunk & 1) * STAGE_BYTES;
            const uint32_t nstage = smem_u32 + (uint32_t)((chunk + 1) & 1) * STAGE_BYTES;
            if (kt + 1 < NKT) {
                load_stage(nstage, kt + 1, rowBase, colBase, tid);
                CP_COMMIT(); CP_WAIT(1);
            } else if (hasNext) {
                load_stage(nstage, 0, nRowBase, nColBase, tid);
                CP_COMMIT(); CP_WAIT(1);
            } else {
                CP_WAIT(0);
            }
            __syncthreads();

            const uint32_t bBase = stage + 16384;
            #pragma unroll
            for (int s = 0; s < 4; s++) {
                uint32_t ah[2][4], bh[4][4];
                #pragma unroll
                for (int mt = 0; mt < 2; mt++)
                    ldsm4(ah[mt], swadr(stage, aRowByte[mt], aRm, 2 * s + aCh));
                #pragma unroll
                for (int p = 0; p < 4; p++)
                    ldsm4(bh[p], swadr(bBase, bRowByte[p], bRm, 2 * s + bCh));
                #pragma unroll
                for (int mt = 0; mt < 2; mt++)
                    #pragma unroll
                    for (int nt = 0; nt < 8; nt++)
                        imma16832(acc[mt][nt], ah[mt], bh[nt >> 1][(nt & 1) * 2],
                                  bh[nt >> 1][(nt & 1) * 2 + 1]);
            }
            __syncthreads();
            chunk++;
        }

        // ---------------- Epilogue (next tile's kt0 load is in flight) -------
        const float l2T = c_l2T;
        const int r8 = lane >> 2;
        float raL[4];
        #pragma unroll
        for (int mt = 0; mt < 2; mt++) {
            raL[mt * 2 + 0] = g_rs[rowBase + warpM * 32 + mt * 16 + 0 + r8] * l2T;
            raL[mt * 2 + 1] = g_rs[rowBase + warpM * 32 + mt * 16 + 8 + r8] * l2T;
        }
        float rbv[16];
        #pragma unroll
        for (int nt = 0; nt < 8; nt++) {
            const int c0 = colBase + warpN * 64 + nt * 8 + (lane & 3) * 2;
            rbv[nt * 2 + 0] = g_rs[c0];
            rbv[nt * 2 + 1] = g_rs[c0 + 1];
        }

        float rs0[2] = {0.0f, 0.0f}, rs1[2] = {0.0f, 0.0f};
        float cs[16];
        #pragma unroll
        for (int i = 0; i < 16; i++) cs[i] = 0.0f;

        #pragma unroll
        for (int mt = 0; mt < 2; mt++)
            #pragma unroll
            for (int nt = 0; nt < 8; nt++) {
                const float f0 = __int2float_rn(acc[mt][nt][0]);
                const float f1 = __int2float_rn(acc[mt][nt][1]);
                const float f2 = __int2float_rn(acc[mt][nt][2]);
                const float f3 = __int2float_rn(acc[mt][nt][3]);
                const float e0 = ex2(f0 * raL[mt * 2 + 0] * rbv[nt * 2 + 0]);
                const float e1 = ex2(f1 * raL[mt * 2 + 0] * rbv[nt * 2 + 1]);
                const float e2 = ex2(f2 * raL[mt * 2 + 1] * rbv[nt * 2 + 0]);
                const float e3 = ex2(f3 * raL[mt * 2 + 1] * rbv[nt * 2 + 1]);
                rs0[mt] += e0 + e1;
                rs1[mt] += e2 + e3;
                cs[nt * 2 + 0] += e0 + e2;
                cs[nt * 2 + 1] += e1 + e3;
            }

        #pragma unroll
        for (int off = 1; off <= 2; off <<= 1) {
            #pragma unroll
            for (int mt = 0; mt < 2; mt++) {
                rs0[mt] += __shfl_xor_sync(0xffffffffu, rs0[mt], off);
                rs1[mt] += __shfl_xor_sync(0xffffffffu, rs1[mt], off);
            }
        }
        if ((lane & 3) == 0) {
            #pragma unroll
            for (int mt = 0; mt < 2; mt++) {
                rowScratch[warpN * 128 + warpM * 32 + mt * 16 + 0 + r8] = rs0[mt];
                rowScratch[warpN * 128 + warpM * 32 + mt * 16 + 8 + r8] = rs1[mt];
            }
        }
        if (sym) {
            #pragma unroll
            for (int i = 0; i < 16; i++) {
                #pragma unroll
                for (int off = 4; off <= 16; off <<= 1)
                    cs[i] += __shfl_xor_sync(0xffffffffu, cs[i], off);
            }
            if (lane < 4) {
                #pragma unroll
                for (int nt = 0; nt < 8; nt++) {
                    colScratch[(warpN * 4 + warpM) * 64 + nt * 8 + lane * 2 + 0] = cs[nt * 2 + 0];
                    colScratch[(warpN * 4 + warpM) * 64 + nt * 8 + lane * 2 + 1] = cs[nt * 2 + 1];
                }
            }
        }
        __syncthreads();

        if (tid < 128) {
            const float p = rowScratch[tid] + rowScratch[128 + tid];
            g_partial[(size_t)(rowBase + tid) * NCOLTILES + colTile] = p;
            if (sym) {
                const int wn = tid >> 6, ix = tid & 63;
                float c = colScratch[(wn * 4 + 0) * 64 + ix] + colScratch[(wn * 4 + 1) * 64 + ix]
                        + colScratch[(wn * 4 + 2) * 64 + ix] + colScratch[(wn * 4 + 3) * 64 + ix];
                g_partial[(size_t)(colBase + tid) * NCOLTILES + bx] = c;
            }
        }
        __syncthreads();   // scratch reuse safety for next tile

        if (!hasNext) break;
        tile = nxtTile; bx = nbx; colTile = nct; sym = nsym;
        rowBase = nRowBase; colBase = nColBase;
    }
}

// ---------------------------------------------------------------------------
// Kernel 3: per-row loss + grid-wide mean (last-block pattern, deterministic).
// g_rs loads hoisted above the reduction chain (latency overlap).
// ---------------------------------------------------------------------------
__global__ void __launch_bounds__(256) loss_reduce_kernel(float* __restrict__ out) {
    __shared__ float warpLoss[8];
    __shared__ int   isLast;
    const int bid  = blockIdx.x;
    const int row  = bid * 8 + (threadIdx.x >> 5);
    const int lane = threadIdx.x & 31;

    // PDL gate: simsum_mma_kernel must be complete before reading g_partial.
    cudaGridDependencySynchronize();

    // Hoist scale loads (needed post-reduction on lane 0 only).
    const float ra = g_rs[row];
    const float rb = g_rs[N_ROWS + row];
    const float rc = g_rs[N_ROWS];

    float total = g_partial[(size_t)row * NCOLTILES + lane]
                + g_partial[(size_t)row * NCOLTILES + lane + 32];

    const uint2 qa = reinterpret_cast<const uint2*>(g_q + (size_t)row * D)[lane];
    const uint2 qb = reinterpret_cast<const uint2*>(g_q + (size_t)(N_ROWS + row) * D)[lane];
    const uint2 qc = reinterpret_cast<const uint2*>(g_q + (size_t)N_ROWS * D)[lane];

    int dpi = __dp4a((int)qa.x, (int)qb.x, 0); dpi = __dp4a((int)qa.y, (int)qb.y, dpi);
    int d0i = __dp4a((int)qa.x, (int)qc.x, 0); d0i = __dp4a((int)qa.y, (int)qc.y, d0i);
    int dii = __dp4a((int)qa.x, (int)qa.x, 0); dii = __dp4a((int)qa.y, (int)qa.y, dii);

    #pragma unroll
    for (int off = 16; off > 0; off >>= 1) {
        total += __shfl_xor_sync(0xffffffffu, total, off);
        dpi   += __shfl_xor_sync(0xffffffffu, dpi, off);
        d0i   += __shfl_xor_sync(0xffffffffu, d0i, off);
        dii   += __shfl_xor_sync(0xffffffffu, dii, off);
    }
    if (lane == 0) {
        const float dp    = __int2float_rn(dpi) * ra * rb;
        const float d0    = __int2float_rn(d0i) * ra * rc;
        const float dii_f = __int2float_rn(dii) * ra * ra;
        float sum_negs = total - ex2(d0 * c_l2T) - ex2(dii_f * c_l2T) + ex2(c_l2T);
        warpLoss[threadIdx.x >> 5] = logf(sum_negs) - dp * c_invT;
    }
    __syncthreads();

    if (threadIdx.x == 0) {
        float bs = 0.0f;
        #pragma unroll
        for (int i = 0; i < 8; i++) bs += warpLoss[i];
        g_blocksum[bid] = bs;
        __threadfence();
        int old = atomicAdd(&g_counter, 1);
        isLast = (old == NLOSSBLK - 1);
    }
    __syncthreads();

    if (isLast) {
        __shared__ float s[256];
        float v = 0.0f;
        #pragma unroll
        for (int h = 0; h < 2; h++) {
            float t;
            asm volatile("ld.global.cg.f32 %0, [%1];" : "=f"(t)
                         : "l"(g_blocksum + threadIdx.x + h * 256));
            v += t;
        }
        s[threadIdx.x] = v;
        __syncthreads();
        #pragma unroll
        for (int stride = 128; stride > 0; stride >>= 1) {
            if (threadIdx.x < stride) s[threadIdx.x] += s[threadIdx.x + stride];
            __syncthreads();
        }
        if (threadIdx.x == 0) {
            out[0] = s[0] * (1.0f / N_ROWS);
            g_counter = 0;   // reset for graph replay
        }
    }
}

// ---------------------------------------------------------------------------
extern "C" void kernel_launch(void* const* d_in, const int* in_sizes, int n_in,
                              void* d_out, int out_size) {
    const float* z1 = (const float*)d_in[0];
    const float* z2 = (const float*)d_in[1];
    float* out = (float*)d_out;

    cudaFuncSetAttribute(simsum_mma_kernel,
                         cudaFuncAttributeMaxDynamicSharedMemorySize, SMEM_TOTAL);

    normalize_kernel<<<TWO_N / 8, 256>>>(z1, z2);

    // PDL launches: overlap dependent kernel prologue with predecessor tail.
    cudaLaunchAttribute attr[1];
    attr[0].id = cudaLaunchAttributeProgrammaticStreamSerialization;
    attr[0].val.programmaticStreamSerializationAllowed = 1;

    {
        cudaLaunchConfig_t cfg = {};
        cfg.gridDim = dim3(GRID_GEMM, 1, 1);
        cfg.blockDim = dim3(256, 1, 1);
        cfg.dynamicSmemBytes = SMEM_TOTAL;
        cfg.attrs = attr;
        cfg.numAttrs = 1;
        cudaLaunchKernelEx(&cfg, simsum_mma_kernel);
    }
    {
        cudaLaunchConfig_t cfg = {};
        cfg.gridDim = dim3(NLOSSBLK, 1, 1);
        cfg.blockDim = dim3(256, 1, 1);
        cfg.dynamicSmemBytes = 0;
        cfg.attrs = attr;
        cfg.numAttrs = 1;
        cudaLaunchKernelEx(&cfg, loss_reduce_kernel, out);
    }
}